// round 12
// baseline (speedup 1.0000x reference)
#include <cuda_runtime.h>
#include <cuda_bf16.h>

#define K_DIM 1024
#define E_DIM 64
#define NVEC  (16 * 64 * 64)        // 65536 vectors
#define NPIX  (16 * 64 * 64 * 64)   // 4194304 output elements (vq part)
#define KC    64                    // codebook entries per smem chunk
#define NCH   (K_DIM / KC)          // 16 chunks
#define NCTA  (NVEC / 64)           // 1024 CTAs x 64 threads, 1 vector/lane

__device__ double       d_loss_acc;   // zero-init; reset by last CTA each call
__device__ unsigned int d_ticket;     // zero-init; reset by last CTA each call

typedef unsigned long long ull;

// ---- packed f32x2 helpers (sm_103a) ----
__device__ __forceinline__ void fma2(ull& d, ull a, ull b) {
    asm("fma.rn.f32x2 %0, %1, %2, %0;" : "+l"(d) : "l"(a), "l"(b));
}
__device__ __forceinline__ void add2(ull& d, ull a) {
    asm("add.rn.f32x2 %0, %0, %1;" : "+l"(d) : "l"(a));
}
__device__ __forceinline__ float2 unpack2(ull v) {
    float2 r; asm("mov.b64 {%0, %1}, %2;" : "=f"(r.x), "=f"(r.y) : "l"(v)); return r;
}
__device__ __forceinline__ ull pack2(float lo, float hi) {
    ull v; asm("mov.b64 %0, {%1, %2};" : "=l"(v) : "f"(lo), "f"(hi)); return v;
}

// Split-E: lane L owns vector n(L); lane pair (2t,2t+1) covers 2 vectors x 64
// dims. Lane with h = L&1 holds dim-pairs p with ((p>>1)&1)==h (i.e. chains
// a_{2h}, a_{2h+1} of the PROVEN 4-chain tree) for BOTH vectors of the pair.
// Per code: 8 LDS.128 per lane (half row), 32 fma2 (2 vec x 16 pairs), one
// shfl.xor(1) to exchange partner partials. Result bits identical to R7:
// (a0+a1)+(a2+a3) with packed-add commutativity, fadd(s.x,s.y),
// fma(-2,dot,fadd(z2,e2)), strict < ascending k.
__global__ __launch_bounds__(64, 7)
void vq_kernel(const float* __restrict__ z,
               const float* __restrict__ cb,
               float* __restrict__ out_vq,
               float* __restrict__ out_loss,
               int has_loss) {
    __shared__ float sh_cb[KC * E_DIM];   // 16 KB
    __shared__ float sh_e2[KC];

    const int tid = threadIdx.x;          // 0..63
    const int h   = tid & 1;              // dim-half of this lane
    const int n   = blockIdx.x * 64 + tid;                  // own vector
    const int base  = (n >> 12) * (E_DIM * 4096) + (n & 4095);
    const int pbase = base + 1 - 2 * h;                     // partner vector (n^1)

    // ---- prologue ----
    // Own vector: sequential pair loop -> z2 (proven rounding order); keep the
    // pairs of my half-pattern in zself (slot 2m+e holds pair 4m+2h+e).
    ull zself[16], zpart[16];
    float z2 = 0.f;
#pragma unroll
    for (int p = 0; p < 32; p++) {
        float lo = z[base + (2 * p)     * 4096];
        float hi = z[base + (2 * p + 1) * 4096];
        z2 = __fadd_rn(z2, __fadd_rn(__fmul_rn(lo, lo), __fmul_rn(hi, hi)));
        if (((p >> 1) & 1) == h)
            zself[(p >> 2) * 2 + (p & 1)] = pack2(lo, hi);
    }
    // Partner vector: only my half-pattern pairs.
#pragma unroll
    for (int m = 0; m < 8; m++) {
#pragma unroll
        for (int e = 0; e < 2; e++) {
            int p = 4 * m + 2 * h + e;
            zpart[2 * m + e] = pack2(z[pbase + (2 * p) * 4096],
                                     z[pbase + (2 * p + 1) * 4096]);
        }
    }

    float best = 3.4e38f;
    int   bidx = 0;

    // ---- main loop over 16 chunks of 64 codes ----
    for (int ch = 0; ch < NCH; ch++) {
        const int k0 = ch * KC;
        __syncthreads();
        {   // cooperative chunk load: 1024 float4 / 64 threads
            const float4* src = reinterpret_cast<const float4*>(cb + k0 * E_DIM);
            float4* dst = reinterpret_cast<float4*>(sh_cb);
#pragma unroll
            for (int i = 0; i < 16; i++)
                dst[tid + i * 64] = src[tid + i * 64];
        }
        __syncthreads();
        {   // e2 row tid: float4-sequential (proven bit-identical)
            const float4* r = reinterpret_cast<const float4*>(sh_cb + tid * E_DIM);
            float s = 0.f;
#pragma unroll
            for (int i = 0; i < E_DIM / 4; i++) {
                float4 v = r[i];
                s += v.x * v.x + v.y * v.y + v.z * v.z + v.w * v.w;
            }
            sh_e2[tid] = s;
        }
        __syncthreads();

        const char* cbb = reinterpret_cast<const char*>(sh_cb) + 16 * h;
#pragma unroll 1
        for (int j = 0; j < KC; j += 2) {
            const char* rA = cbb + (j    ) * 256;
            const char* rB = cbb + (j + 1) * 256;
            ull sA0 = 0, sA1 = 0, pA0 = 0, pA1 = 0;   // code j  : own / partner
            ull sB0 = 0, sB1 = 0, pB0 = 0, pB1 = 0;   // code j+1
#pragma unroll
            for (int m = 0; m < 8; m++) {             // 4 LDS.128 + 16 fma2 /2m
                ulonglong2 eA = *reinterpret_cast<const ulonglong2*>(rA + 32 * m);
                ulonglong2 eB = *reinterpret_cast<const ulonglong2*>(rB + 32 * m);
                fma2(sA0, zself[2 * m],     eA.x);
                fma2(pA0, zpart[2 * m],     eA.x);
                fma2(sA1, zself[2 * m + 1], eA.y);
                fma2(pA1, zpart[2 * m + 1], eA.y);
                fma2(sB0, zself[2 * m],     eB.x);
                fma2(pB0, zpart[2 * m],     eB.x);
                fma2(sB1, zself[2 * m + 1], eB.y);
                fma2(pB1, zpart[2 * m + 1], eB.y);
            }
            // own-half sums (= a_{2h}+a_{2h+1}) and partner-vector half sums
            add2(sA0, sA1);  add2(pA0, pA1);
            add2(sB0, sB1);  add2(pB0, pB1);
            // exchange: send my partial of partner's vector, receive the
            // partner's partial of MY vector.
            ull rAv = __shfl_xor_sync(0xFFFFFFFFu, pA0, 1);
            ull rBv = __shfl_xor_sync(0xFFFFFFFFu, pB0, 1);
            add2(sA0, rAv);                 // (a0+a1)+(a2+a3), commutative
            add2(sB0, rBv);
            float2 sa = unpack2(sA0);
            float2 sb = unpack2(sB0);
            float dotA = __fadd_rn(sa.x, sa.y);
            float dotB = __fadd_rn(sb.x, sb.y);
            float2 e2v = *reinterpret_cast<const float2*>(sh_e2 + j);
            float dA = __fmaf_rn(-2.0f, dotA, __fadd_rn(z2, e2v.x));
            if (dA < best) { best = dA; bidx = k0 + j; }
            float dB = __fmaf_rn(-2.0f, dotB, __fadd_rn(z2, e2v.y));
            if (dB < best) { best = dB; bidx = k0 + j + 1; }
        }
    }

    // ---- epilogue: gather winner (L2-resident), write vq, loss ----
    const float2* er = reinterpret_cast<const float2*>(cb + bidx * E_DIM);
    float local = 0.f;
#pragma unroll
    for (int i = 0; i < E_DIM / 2; i++) {
        float2 e = __ldg(&er[i]);
        float p0 = __ldg(&z[base + (2 * i)     * 4096]);
        float p1 = __ldg(&z[base + (2 * i + 1) * 4096]);
        float q0 = e.x - p0, q1 = e.y - p1;
        local += q0 * q0 + q1 * q1;
        out_vq[base + (2 * i)     * 4096] = e.x;
        out_vq[base + (2 * i + 1) * 4096] = e.y;
    }
#pragma unroll
    for (int o = 16; o; o >>= 1)
        local += __shfl_xor_sync(0xFFFFFFFFu, local, o);
    if ((tid & 31) == 0)
        atomicAdd(&d_loss_acc, (double)local);

    // Last-CTA finalize (self-resetting: deterministic across graph replays).
    __syncthreads();
    if (tid == 0) {
        __threadfence();
        unsigned int done = atomicAdd(&d_ticket, 1u);
        if (done == (unsigned int)(NCTA - 1)) {
            if (has_loss)
                *out_loss = (float)(1.25 * d_loss_acc / (double)NPIX);
            d_loss_acc = 0.0;
            d_ticket   = 0u;
            __threadfence();
        }
    }
}

extern "C" void kernel_launch(void* const* d_in, const int* in_sizes, int n_in,
                              void* d_out, int out_size) {
    // metadata order: z [16,64,64,64] fp32, codebook [1024,64] fp32.
    const float* z  = (const float*)d_in[0];
    const float* cb = (const float*)d_in[1];
    if (n_in >= 2 && in_sizes[0] == K_DIM * E_DIM && in_sizes[1] == NPIX) {
        const float* t = z; z = cb; cb = t;   // defensive: inputs swapped
    }

    float* out = (float*)d_out;
    int voff = out_size - NPIX;            // 1 if scalar loss precedes vq_out
    if (voff < 0) voff = 0;
    float* out_vq = out + voff;

    vq_kernel<<<NCTA, 64>>>(z, cb, out_vq, out, voff > 0 ? 1 : 0);
}

// round 13
// speedup vs baseline: 1.2774x; 1.2774x over previous
#include <cuda_runtime.h>
#include <cuda_bf16.h>

#define K_DIM 1024
#define E_DIM 64
#define NVEC  (16 * 64 * 64)        // 65536 vectors
#define NPIX  (16 * 64 * 64 * 64)   // 4194304 output elements (vq part)
#define KC    128                   // codebook entries per smem chunk
#define NCH   (K_DIM / KC)          // 8 chunks
#define NCTA  (NVEC / 256)          // 256 CTAs, 128 thr, T=2 vectors/thread

__device__ double       d_loss_acc;   // zero-init; reset by last CTA each call
__device__ unsigned int d_ticket;     // zero-init; reset by last CTA each call

typedef unsigned long long ull;

// ---- packed f32x2 helpers (sm_103a) ----
__device__ __forceinline__ void fma2(ull& d, ull a, ull b) {
    asm("fma.rn.f32x2 %0, %1, %2, %0;" : "+l"(d) : "l"(a), "l"(b));
}
__device__ __forceinline__ void add2(ull& d, ull a) {
    asm("add.rn.f32x2 %0, %0, %1;" : "+l"(d) : "l"(a));
}
__device__ __forceinline__ float2 unpack2(ull v) {
    float2 r; asm("mov.b64 {%0, %1}, %2;" : "=f"(r.x), "=f"(r.y) : "l"(v)); return r;
}
__device__ __forceinline__ ull pack2(float lo, float hi) {
    ull v; asm("mov.b64 %0, {%1, %2};" : "=l"(v) : "f"(lo), "f"(hi)); return v;
}

// R7 body (bit-identical arithmetic per (vec,code): 4-chain f32x2 tree with
// chain c over pairs p===c mod 4 ascending, dot=fadd(lo,hi),
// dist=fma(-2,dot,fadd(z2,e2)), strict < ascending k) with a 2-stage half-row
// register pipeline: the LDS for each half-row is issued one FMA-stage before
// its use, hiding the 29-cyc LDS latency that capped R7 at ~61% of the fma
// floor. Single fused launch (in-chunk e2 + ticket finalize).
__global__ __launch_bounds__(128, 2)
void vq_kernel(const float* __restrict__ z,
               const float* __restrict__ cb,
               float* __restrict__ out_vq,
               float* __restrict__ out_loss,
               int has_loss) {
    __shared__ float sh_cb[KC * E_DIM];   // 32 KB
    __shared__ float sh_e2[KC];

    const int tid = threadIdx.x;
    const int n0  = blockIdx.x * 256 + tid;     // vector ids n0 and n0+128
    const int n1  = n0 + 128;
    const int base0 = (n0 >> 12) * (E_DIM * 4096) + (n0 & 4095);
    const int base1 = (n1 >> 12) * (E_DIM * 4096) + (n1 & 4095);

    // Both z rows in registers as packed f32x2 (128 regs).
    ull zr0[E_DIM / 2], zr1[E_DIM / 2];
#pragma unroll
    for (int i = 0; i < E_DIM / 2; i++) {
        zr0[i] = pack2(z[base0 + (2 * i) * 4096], z[base0 + (2 * i + 1) * 4096]);
        zr1[i] = pack2(z[base1 + (2 * i) * 4096], z[base1 + (2 * i + 1) * 4096]);
    }

    // ||z||^2 fp32, sequential pair order (reference-matching rounding anchor).
    float z20 = 0.f, z21 = 0.f;
#pragma unroll
    for (int i = 0; i < E_DIM / 2; i++) {
        float2 v0 = unpack2(zr0[i]);
        float2 v1 = unpack2(zr1[i]);
        z20 = __fadd_rn(z20, __fadd_rn(__fmul_rn(v0.x, v0.x), __fmul_rn(v0.y, v0.y)));
        z21 = __fadd_rn(z21, __fadd_rn(__fmul_rn(v1.x, v1.x), __fmul_rn(v1.y, v1.y)));
    }

    float best0 = 3.4e38f, best1 = 3.4e38f;
    int   bidx0 = 0,       bidx1 = 0;

    for (int k0 = 0; k0 < K_DIM; k0 += KC) {
        __syncthreads();
        // Cooperative chunk load: KC*64 floats = 2048 float4 / 128 threads
        {
            const float4* src = reinterpret_cast<const float4*>(cb + k0 * E_DIM);
            float4* dst = reinterpret_cast<float4*>(sh_cb);
#pragma unroll
            for (int i = 0; i < (KC * E_DIM / 4) / 128; i++)
                dst[tid + i * 128] = src[tid + i * 128];
        }
        __syncthreads();
        // e2 row tid of this chunk: float4-sequential (proven bit-identical).
        {
            const float4* r = reinterpret_cast<const float4*>(sh_cb + tid * E_DIM);
            float s = 0.f;
#pragma unroll
            for (int i = 0; i < E_DIM / 4; i++) {
                float4 v = r[i];
                s += v.x * v.x + v.y * v.y + v.z * v.z + v.w * v.w;
            }
            sh_e2[tid] = s;
        }
        __syncthreads();

        const ulonglong2* rows = reinterpret_cast<const ulonglong2*>(sh_cb);
        // Prime pipeline: H0 of code 0 (pairs 0..15 = entries 0..7).
        ulonglong2 bufA[8];
#pragma unroll
        for (int e = 0; e < 8; e++) bufA[e] = rows[e];

#pragma unroll 1
        for (int j = 0; j < KC; j++) {
            const ulonglong2* ej  = rows + j * 16;
            const ulonglong2* ejn = rows + ((j + 1 < KC) ? (j + 1) : 0) * 16;

            // Stage-1 loads: H1(j) (pairs 16..31).
            ulonglong2 bufB[8];
#pragma unroll
            for (int e = 0; e < 8; e++) bufB[e] = ej[8 + e];

            ull a0 = 0, a1 = 0, a2 = 0, a3 = 0;   // vec0 chains (p mod 4)
            ull b0 = 0, b1 = 0, b2 = 0, b3 = 0;   // vec1 chains

            // Stage-1 FMA on bufA: pairs 0..15 (chain entries 0..3).
#pragma unroll
            for (int i = 0; i < 4; i++) {
                ulonglong2 x0 = bufA[2 * i];
                ulonglong2 x1 = bufA[2 * i + 1];
                fma2(a0, zr0[4 * i + 0], x0.x);
                fma2(b0, zr1[4 * i + 0], x0.x);
                fma2(a1, zr0[4 * i + 1], x0.y);
                fma2(b1, zr1[4 * i + 1], x0.y);
                fma2(a2, zr0[4 * i + 2], x1.x);
                fma2(b2, zr1[4 * i + 2], x1.x);
                fma2(a3, zr0[4 * i + 3], x1.y);
                fma2(b3, zr1[4 * i + 3], x1.y);
            }

            // Stage-2 loads: H0(j+1) into bufA (consumed next iteration).
#pragma unroll
            for (int e = 0; e < 8; e++) bufA[e] = ejn[e];

            // Stage-2 FMA on bufB: pairs 16..31 (chain entries 4..7).
#pragma unroll
            for (int i = 0; i < 4; i++) {
                ulonglong2 x0 = bufB[2 * i];
                ulonglong2 x1 = bufB[2 * i + 1];
                fma2(a0, zr0[16 + 4 * i + 0], x0.x);
                fma2(b0, zr1[16 + 4 * i + 0], x0.x);
                fma2(a1, zr0[16 + 4 * i + 1], x0.y);
                fma2(b1, zr1[16 + 4 * i + 1], x0.y);
                fma2(a2, zr0[16 + 4 * i + 2], x1.x);
                fma2(b2, zr1[16 + 4 * i + 2], x1.x);
                fma2(a3, zr0[16 + 4 * i + 3], x1.y);
                fma2(b3, zr1[16 + 4 * i + 3], x1.y);
            }

            // Reduction tree + dist: identical bits to rounds 3/7.
            add2(a0, a1); add2(a2, a3); add2(a0, a2);
            add2(b0, b1); add2(b2, b3); add2(b0, b2);
            float2 s0 = unpack2(a0);
            float2 s1 = unpack2(b0);
            float dot0 = __fadd_rn(s0.x, s0.y);
            float dot1 = __fadd_rn(s1.x, s1.y);
            float e2j  = sh_e2[j];
            float d0 = __fmaf_rn(-2.0f, dot0, __fadd_rn(z20, e2j));
            if (d0 < best0) { best0 = d0; bidx0 = k0 + j; }
            float d1 = __fmaf_rn(-2.0f, dot1, __fadd_rn(z21, e2j));
            if (d1 < best1) { best1 = d1; bidx1 = k0 + j; }
        }
    }

    // Epilogue: gather winning rows (L2-resident), write vq, accumulate loss.
    float local = 0.f;
    {
        const float2* er = reinterpret_cast<const float2*>(cb + bidx0 * E_DIM);
#pragma unroll
        for (int i = 0; i < E_DIM / 2; i++) {
            float2 e  = __ldg(&er[i]);
            float2 zp = unpack2(zr0[i]);
            float q0 = e.x - zp.x, q1 = e.y - zp.y;
            local += q0 * q0 + q1 * q1;
            out_vq[base0 + (2 * i)     * 4096] = e.x;
            out_vq[base0 + (2 * i + 1) * 4096] = e.y;
        }
    }
    {
        const float2* er = reinterpret_cast<const float2*>(cb + bidx1 * E_DIM);
#pragma unroll
        for (int i = 0; i < E_DIM / 2; i++) {
            float2 e  = __ldg(&er[i]);
            float2 zp = unpack2(zr1[i]);
            float q0 = e.x - zp.x, q1 = e.y - zp.y;
            local += q0 * q0 + q1 * q1;
            out_vq[base1 + (2 * i)     * 4096] = e.x;
            out_vq[base1 + (2 * i + 1) * 4096] = e.y;
        }
    }

    // warp reduce + one double atomic per warp
#pragma unroll
    for (int o = 16; o; o >>= 1)
        local += __shfl_xor_sync(0xFFFFFFFFu, local, o);
    if ((tid & 31) == 0)
        atomicAdd(&d_loss_acc, (double)local);

    // Last-CTA finalize (self-resetting: deterministic across graph replays).
    __syncthreads();
    if (tid == 0) {
        __threadfence();
        unsigned int done = atomicAdd(&d_ticket, 1u);
        if (done == (unsigned int)(NCTA - 1)) {
            if (has_loss)
                *out_loss = (float)(1.25 * d_loss_acc / (double)NPIX);
            d_loss_acc = 0.0;
            d_ticket   = 0u;
            __threadfence();
        }
    }
}

extern "C" void kernel_launch(void* const* d_in, const int* in_sizes, int n_in,
                              void* d_out, int out_size) {
    // metadata order: z [16,64,64,64] fp32, codebook [1024,64] fp32.
    const float* z  = (const float*)d_in[0];
    const float* cb = (const float*)d_in[1];
    if (n_in >= 2 && in_sizes[0] == K_DIM * E_DIM && in_sizes[1] == NPIX) {
        const float* t = z; z = cb; cb = t;   // defensive: inputs swapped
    }

    float* out = (float*)d_out;
    int voff = out_size - NPIX;            // 1 if scalar loss precedes vq_out
    if (voff < 0) voff = 0;
    float* out_vq = out + voff;

    vq_kernel<<<NCTA, 128>>>(z, cb, out_vq, out, voff > 0 ? 1 : 0);
}